// round 4
// baseline (speedup 1.0000x reference)
#include <cuda_runtime.h>
#include <cstdint>

// ---------------- problem dims (fixed by dataset) ----------------
#define S_LEN  512
#define BATCH  512
#define VOCAB  50000
#define EDIM   50
#define HDIM   128
#define G3     384          // 3*H
#define NROWS  1024         // 2 sequences * BATCH

typedef unsigned long long ull;

// ---------------- device scratch (no cudaMalloc allowed) ----------------
__device__ float g_emb_proj[(size_t)VOCAB * G3];   // 76.8 MB: W_ih @ emb[v] + b_ih
__device__ float g_hfinal[NROWS * HDIM];           // rows 0..511 = seq1, 512..1023 = seq2

// ---------------- helpers ----------------
__device__ __forceinline__ void ffma2(ull &acc, ull a, ull b) {
    asm("fma.rn.f32x2 %0, %1, %2, %0;" : "+l"(acc) : "l"(a), "l"(b));
}
__device__ __forceinline__ float lane_sum(ull v) {
    float lo = __uint_as_float((unsigned)(v & 0xffffffffu));
    float hi = __uint_as_float((unsigned)(v >> 32));
    return lo + hi;
}
__device__ __forceinline__ float sigf(float x) {
    return __fdividef(1.f, 1.f + __expf(-x));
}

// =================================================================
// Kernel A: emb_proj[v][g] = b_ih[g] + sum_e emb[v][e] * W_ih[g][e]
// 384 threads (thread = gate row g), 64 vocab rows per block.
// =================================================================
#define A_VB 64

__global__ __launch_bounds__(384) void emb_proj_kernel(
        const float* __restrict__ emb,
        const float* __restrict__ W_ih,
        const float* __restrict__ b_ih) {
    __shared__ __align__(16) float emb_s[A_VB * 52];   // padded pitch 52

    const int g  = threadIdx.x;                        // 0..383
    const int v0 = blockIdx.x * A_VB;

    // stage emb tile (coalesced)
    for (int idx = g; idx < A_VB * EDIM; idx += 384) {
        int v = idx / EDIM, e = idx % EDIM;
        float val = 0.f;
        if (v0 + v < VOCAB) val = emb[(size_t)(v0 + v) * EDIM + e];
        emb_s[v * 52 + e] = val;
    }

    // this thread's W_ih row as 25 packed pairs (byte offset g*200, 8B aligned)
    ull w2[25];
    const ull* wrow = reinterpret_cast<const ull*>(W_ih + g * EDIM);
#pragma unroll
    for (int ep = 0; ep < 25; ep++) w2[ep] = __ldg(&wrow[ep]);
    const float bias = __ldg(&b_ih[g]);

    __syncthreads();

    for (int v = 0; v < A_VB; v++) {
        if (v0 + v >= VOCAB) break;
        ull acc = 0ull;
        const ull* er = reinterpret_cast<const ull*>(&emb_s[v * 52]);
#pragma unroll
        for (int ep = 0; ep < 25; ep++) ffma2(acc, w2[ep], er[ep]);
        g_emb_proj[(size_t)(v0 + v) * G3 + g] = lane_sum(acc) + bias;  // coalesced over g
    }
}

// =================================================================
// Kernel B: persistent GRU recurrence, both sequences in one launch.
// 128 CTAs x 8 batch-rows, 384 threads (thread g = gate row).
// Dynamic SMEM layout (floats):
//   W_s  [384*132]  (W_hh, padded pitch 132 -> conflict-free LDS.128)
//   h_s  [8*128]
//   A_s  [8*384]    (gx+ghh for r,z parts; ghh for n part)
//   B_s  [8*128]    (gx for n part)
//   tok  [8] ints
// =================================================================
#define WPITCH 132
#define OFF_H   (384 * WPITCH)          // 50688
#define OFF_A   (OFF_H + 8 * HDIM)      // 51712
#define OFF_B   (OFF_A + 8 * G3)        // 54784
#define OFF_TOK (OFF_B + 8 * HDIM)      // 55808
#define SMEM_B_FLOATS (OFF_TOK + 8)     // 55816
#define SMEM_B_BYTES  (SMEM_B_FLOATS * 4)   // 223264

__global__ __launch_bounds__(384, 1) void gru_kernel(
        const int*   __restrict__ x1,
        const int*   __restrict__ x2,
        const float* __restrict__ W_hh,
        const float* __restrict__ b_hh) {
    extern __shared__ __align__(16) float sm[];
    float* W_s = sm;
    float* h_s = sm + OFF_H;
    float* A_s = sm + OFF_A;
    float* B_s = sm + OFF_B;
    int*   tok = (int*)(sm + OFF_TOK);

    const int g    = threadIdx.x;          // 0..383
    const int row0 = blockIdx.x * 8;       // 8 rows per CTA

    // stage W_hh (384x128) into padded SMEM, coalesced
    for (int idx = g; idx < G3 * HDIM; idx += 384) {
        int gg = idx >> 7, kk = idx & 127;
        W_s[gg * WPITCH + kk] = W_hh[idx];
    }
    // h = 0
    for (int idx = g; idx < 8 * HDIM; idx += 384) h_s[idx] = 0.f;
    // tokens for step 0
    if (g < 8) {
        int row = row0 + g;
        tok[g] = (row < BATCH ? x1 : x2)[0 * BATCH + (row & (BATCH - 1))];
    }
    const float bhh = __ldg(&b_hh[g]);
    __syncthreads();

    const ulonglong2* Wrow = reinterpret_cast<const ulonglong2*>(&W_s[g * WPITCH]);

    for (int t = 0; t < S_LEN; t++) {
        // ---- gather gx for each of 8 rows (coalesced over g; issued early,
        //      latency hidden under the dot-product loop) ----
        float gxv[8];
#pragma unroll
        for (int r = 0; r < 8; r++)
            gxv[r] = __ldg(&g_emb_proj[(size_t)tok[r] * G3 + g]);

        // ---- ghh[g][r] = sum_k W_hh[g][k] * h[r][k]  (packed f32x2) ----
        ull acc2[8];
#pragma unroll
        for (int r = 0; r < 8; r++) acc2[r] = 0ull;

#pragma unroll 4
        for (int kq = 0; kq < 32; kq++) {          // 4 floats per iter
            ulonglong2 w = Wrow[kq];
#pragma unroll
            for (int r = 0; r < 8; r++) {
                ulonglong2 hv = reinterpret_cast<const ulonglong2*>(&h_s[r * HDIM])[kq];
                ffma2(acc2[r], w.x, hv.x);
                ffma2(acc2[r], w.y, hv.y);
            }
        }

        // ---- publish gate pre-activations ----
#pragma unroll
        for (int r = 0; r < 8; r++) {
            float a = lane_sum(acc2[r]) + bhh;
            if (g < 2 * HDIM) {
                A_s[r * G3 + g] = a + gxv[r];      // r,z: gx + ghh
            } else {
                A_s[r * G3 + g] = a;               // n: ghh only
                B_s[r * HDIM + (g - 2 * HDIM)] = gxv[r];
            }
        }
        __syncthreads();

        // ---- gate math + h update (1024 items over 384 threads) ----
        for (int item = g; item < 8 * HDIM; item += 384) {
            int r = item >> 7, j = item & 127;
            float rr = sigf(A_s[r * G3 + j]);
            float zz = sigf(A_s[r * G3 + HDIM + j]);
            float nn = tanhf(B_s[r * HDIM + j] + rr * A_s[r * G3 + 2 * HDIM + j]);
            float hv = h_s[item];
            h_s[item] = (1.f - zz) * nn + zz * hv;
        }
        // tokens for next step
        if (t + 1 < S_LEN && g < 8) {
            int row = row0 + g;
            tok[g] = (row < BATCH ? x1 : x2)[(t + 1) * BATCH + (row & (BATCH - 1))];
        }
        __syncthreads();
    }

    // write final hidden states
    for (int item = g; item < 8 * HDIM; item += 384) {
        int r = item >> 7, j = item & 127;
        g_hfinal[(row0 + r) * HDIM + j] = h_s[item];
    }
}

// =================================================================
// Kernel C: head.  out[b] = sigmoid( W2 . relu(W1 . [h1;h2] + b1) + b2 )
// 512 blocks (one per batch element), 128 threads (one per hidden unit).
// =================================================================
__global__ __launch_bounds__(128) void head_kernel(
        const float* __restrict__ W1, const float* __restrict__ b1,
        const float* __restrict__ W2, const float* __restrict__ b2,
        float* __restrict__ out) {
    __shared__ float fc[2 * HDIM];
    __shared__ float red[HDIM];
    const int b = blockIdx.x, j = threadIdx.x;

    fc[j]        = g_hfinal[b * HDIM + j];
    fc[HDIM + j] = g_hfinal[(BATCH + b) * HDIM + j];
    __syncthreads();

    float acc = __ldg(&b1[j]);
    const float* wr = W1 + j * 2 * HDIM;
#pragma unroll 8
    for (int k = 0; k < 2 * HDIM; k++) acc = fmaf(fc[k], __ldg(&wr[k]), acc);
    float hid = fmaxf(acc, 0.f);

    red[j] = hid * __ldg(&W2[j]);
    __syncthreads();
    for (int s = 64; s > 0; s >>= 1) {
        if (j < s) red[j] += red[j + s];
        __syncthreads();
    }
    if (j == 0) out[b] = __fdividef(1.f, 1.f + __expf(-(red[0] + __ldg(&b2[0]))));
}

// =================================================================
// launch
// =================================================================
extern "C" void kernel_launch(void* const* d_in, const int* in_sizes, int n_in,
                              void* d_out, int out_size) {
    const int*   x1   = (const int*)  d_in[0];
    const int*   x2   = (const int*)  d_in[1];
    const float* emb  = (const float*)d_in[2];
    const float* W_ih = (const float*)d_in[3];
    const float* W_hh = (const float*)d_in[4];
    const float* b_ih = (const float*)d_in[5];
    const float* b_hh = (const float*)d_in[6];
    const float* W1   = (const float*)d_in[7];
    const float* b1   = (const float*)d_in[8];
    const float* W2   = (const float*)d_in[9];
    const float* b2   = (const float*)d_in[10];
    float* out = (float*)d_out;

    cudaFuncSetAttribute(gru_kernel,
                         cudaFuncAttributeMaxDynamicSharedMemorySize, SMEM_B_BYTES);

    const int a_blocks = (VOCAB + A_VB - 1) / A_VB;   // 782
    emb_proj_kernel<<<a_blocks, 384>>>(emb, W_ih, b_ih);
    gru_kernel<<<NROWS / 8, 384, SMEM_B_BYTES>>>(x1, x2, W_hh, b_hh);
    head_kernel<<<BATCH, 128>>>(W1, b1, W2, b2, out);
}